// round 8
// baseline (speedup 1.0000x reference)
#include <cuda_runtime.h>

// ---------------------------------------------------------------------------
// HierarchicalBlockShuffleLayer (R7): zero-masked block weights.
//   out[32r+s] = rs*A + (mu*rs)*C2[r,s] + C1[r,s]
//   A = monarch(M) + blockdiag(T); block FMAs reuse the monarch LDS streams
//   with per-lane zero-masked weights (TrH/TrL/TqH/TqL), eliminating the two
//   extra LDS.128 per b. M moved to smem (2 lane-indexed LDS.32/b) to keep
//   register count flat. gamma hoisted to smem (loaded once per block).
// Tile layout unchanged from R6: offset(D) = D*36 + 8*(D>>4).
// ---------------------------------------------------------------------------

typedef unsigned long long u64;

#define THREADS 512
#define XSTR 36

__device__ __forceinline__ u64 pack2(float a, float b) {
    u64 r; asm("mov.b64 %0, {%1, %2};" : "=l"(r) : "f"(a), "f"(b)); return r;
}
__device__ __forceinline__ u64 dup2(float a) { return pack2(a, a); }
__device__ __forceinline__ void unpack2(float& a, float& b, u64 v) {
    asm("mov.b64 {%0, %1}, %2;" : "=f"(a), "=f"(b) : "l"(v));
}
__device__ __forceinline__ u64 fma2(u64 a, u64 b, u64 c) {
    u64 d; asm("fma.rn.f32x2 %0, %1, %2, %3;" : "=l"(d) : "l"(a), "l"(b), "l"(c)); return d;
}

// smem floats: XP 37376 | Msm 1024 | GS 1024 | SPART 128
#define XP_FLOATS   37376
#define OFF_MSM     37376
#define OFF_GS      38400
#define OFF_SPART   39424
#define SMEM_FLOATS 39552
#define SMEM_BYTES  (SMEM_FLOATS * 4)
#define CHUNK_STRIDE 1168            // offset(32r) = r * (32*36 + 16)
#define HI_OFF 584                   // offset(32r+16) - offset(32r)

__global__ void __launch_bounds__(THREADS, 1)
hbsl_kernel(const float* __restrict__ x,
            const float* __restrict__ gamma,
            const float* __restrict__ beta,
            const float* __restrict__ bw,
            const float* __restrict__ wrow,
            const float* __restrict__ wcol,
            const float* __restrict__ alphap,
            const float* __restrict__ bias,
            float* __restrict__ out,
            int ntiles) {
    extern __shared__ float XP[];
    float* Msm   = XP + OFF_MSM;        // M[c][lane]
    float* GS    = XP + OFF_GS;         // gamma
    float* SPART = XP + OFF_SPART;      // [8 quads][2 halves][8]

    const int t = threadIdx.x;
    const int w = t >> 5, l = t & 31;
    const int r = w, q = 31 - w;
    const bool pHi = (l < 16);

    // ---- per-block constant build (once; amortized over ~7 tiles) ----
    float C1r, C2r, C1q, C2q;
    float TrH[16], TrL[16], TqH[16], TqL[16];
    {
        float Mreg[32];
        const float alpha = __ldg(alphap);
        {
            float wrl[32];
#pragma unroll
            for (int k = 0; k < 32; k++) wrl[k] = __ldg(wrow + l * 32 + k);
#pragma unroll
            for (int c = 0; c < 32; c++) {
                float acc = 0.f;
#pragma unroll
                for (int k = 0; k < 32; k++) acc += __ldg(wcol + c * 32 + k) * wrl[k];
                Mreg[c] = alpha * acc;
            }
        }
        if (w == 0) {                 // warp 0 publishes M columns to smem
#pragma unroll
            for (int c = 0; c < 32; c++) Msm[c * 32 + l] = Mreg[c];
        }
        for (int i = t; i < 1024; i += THREADS) GS[i] = __ldg(gamma + i);

        const int off = pHi ? 16 : 0;
        const int jf  = pHi ? (15 - l) : (31 - l);
        const int grpR = pHi ? (63 - 2 * r) : (62 - 2 * r);
        const int grpQ = pHi ? (63 - 2 * q) : (62 - 2 * q);
        float Gm = 0.f, Bm = 0.f, Gmq = 0.f, Bmq = 0.f;
#pragma unroll
        for (int c = 0; c < 32; c++) {
            Gm  += __ldg(gamma + 32 * r + c) * Mreg[c];
            Bm  += __ldg(beta  + 32 * r + c) * Mreg[c];
            Gmq += __ldg(gamma + 32 * q + c) * Mreg[c];
            Bmq += __ldg(beta  + 32 * q + c) * Mreg[c];
        }
        float Gb = 0.f, Bb = 0.f, Gbq = 0.f, Bbq = 0.f;
#pragma unroll
        for (int b = 0; b < 16; b++) {
            const float Trv = __ldg(bw + grpR * 256 + b * 16 + jf);
            const float Tqv = __ldg(bw + grpQ * 256 + b * 16 + jf);
            TrH[b] = pHi ? Trv : 0.f;  TrL[b] = pHi ? 0.f : Trv;
            TqH[b] = pHi ? Tqv : 0.f;  TqL[b] = pHi ? 0.f : Tqv;
            Gb  += __ldg(gamma + 32 * q + off + b) * Trv;
            Bb  += __ldg(beta  + 32 * q + off + b) * Trv;
            Gbq += __ldg(gamma + 32 * r + off + b) * Tqv;
            Bbq += __ldg(beta  + 32 * r + off + b) * Tqv;
        }
        C1r = Bm + Bb + __ldg(bias + 32 * r + l);
        C2r = -(Gm + Gb);
        C1q = Bmq + Bbq + __ldg(bias + 32 * q + l);
        C2q = -(Gmq + Gbq);
    }
    __syncthreads();

    // loader role: quad la = w&7 (rows 4la..4la+3), half lh = w>>3 (dims 512lh..)
    const int la = w & 7, lh = w >> 3;

    const float* mr0 = XP + r * CHUNK_STRIDE;
    const float* mr1 = XP + r * CHUNK_STRIDE + HI_OFF;
    const float* mq0 = XP + q * CHUNK_STRIDE;
    const float* mq1 = XP + q * CHUNK_STRIDE + HI_OFF;

    for (int tile = blockIdx.x; tile < ntiles; tile += gridDim.x) {
        const size_t base = (size_t)tile * 32768;   // 32 rows * 1024

        // ---- load: 4 rows x 512 dims per warp; STS.128 conflict-free ----
        {
            const float* xb = x + base + (size_t)(4 * la) * 1024 + lh * 512;
            const float* gs = GS + lh * 512;
            float s0 = 0.f, s1 = 0.f, s2 = 0.f, s3 = 0.f;
            float p0 = 0.f, p1 = 0.f, p2 = 0.f, p3 = 0.f;
#pragma unroll
            for (int k = 0; k < 16; k++) {
                const int dl = k * 32 + l;
                const int d  = lh * 512 + dl;             // global dim
                const float v0 = __ldg(xb + dl);
                const float v1 = __ldg(xb + 1024 + dl);
                const float v2 = __ldg(xb + 2048 + dl);
                const float v3 = __ldg(xb + 3072 + dl);
                const float g  = gs[dl];                  // smem, 1 wf
                s0 += v0; p0 += v0 * v0;
                s1 += v1; p1 += v1 * v1;
                s2 += v2; p2 += v2 * v2;
                s3 += v3; p3 += v3 * v3;
                float4 vv = make_float4(v0 * g, v1 * g, v2 * g, v3 * g);
                *(float4*)(XP + d * XSTR + (d >> 4) * 8 + 4 * la) = vv;
            }
#pragma unroll
            for (int o2 = 16; o2 > 0; o2 >>= 1) {
                s0 += __shfl_xor_sync(~0u, s0, o2);
                s1 += __shfl_xor_sync(~0u, s1, o2);
                s2 += __shfl_xor_sync(~0u, s2, o2);
                s3 += __shfl_xor_sync(~0u, s3, o2);
                p0 += __shfl_xor_sync(~0u, p0, o2);
                p1 += __shfl_xor_sync(~0u, p1, o2);
                p2 += __shfl_xor_sync(~0u, p2, o2);
                p3 += __shfl_xor_sync(~0u, p3, o2);
            }
            if (l == 0) {
                float* sp = SPART + (la * 2 + lh) * 8;
                sp[0] = s0; sp[1] = s1; sp[2] = s2; sp[3] = s3;
                sp[4] = p0; sp[5] = p1; sp[6] = p2; sp[7] = p3;
            }
        }
        __syncthreads();

        // ---- stats finalize, redundant per warp: lane l -> row l ----
        float rs_l, murs_l;
        {
            const int a2 = l >> 2, jj = l & 3;
            const float s = SPART[(a2 * 2) * 8 + jj]     + SPART[(a2 * 2 + 1) * 8 + jj];
            const float p = SPART[(a2 * 2) * 8 + 4 + jj] + SPART[(a2 * 2 + 1) * 8 + 4 + jj];
            const float mu = s * (1.f / 1024.f);
            rs_l   = rsqrtf(p * (1.f / 1024.f) - mu * mu + 1e-5f);
            murs_l = mu * rs_l;
        }

        // ---- L2 prefetch of next tile (this warp's own load region) ----
        {
            const int nt = tile + gridDim.x;
            if (nt < ntiles) {
                const char* pn = (const char*)(x + (size_t)nt * 32768 +
                                               (size_t)(4 * la) * 1024 + lh * 512);
#pragma unroll
                for (int j = 0; j < 2; j++) {
                    const int line = 2 * l + j;
                    const int row = line >> 4, kk = line & 15;
                    asm volatile("prefetch.global.L2 [%0];"
                                 :: "l"(pn + (size_t)row * 4096 + kk * 128));
                }
            }
        }

        // ---- compute: 8 row-quads; per b: 4 LDS.128 + 2 LDS.32, 16 fma2 ----
#pragma unroll 1
        for (int a = 0; a < 8; a++) {
            const int go = 4 * a;
            u64 ar0 = 0, ar1 = 0, aq0 = 0, aq1 = 0;
#pragma unroll
            for (int b = 0; b < 16; b++) {
                const ulonglong2 xrL = *(const ulonglong2*)(mr0 + b * XSTR + go);
                const ulonglong2 xrH = *(const ulonglong2*)(mr1 + b * XSTR + go);
                const ulonglong2 xqL = *(const ulonglong2*)(mq0 + b * XSTR + go);
                const ulonglong2 xqH = *(const ulonglong2*)(mq1 + b * XSTR + go);
                const u64 mL = dup2(Msm[b * 32 + l]);          // LDS.32, 1 wf
                const u64 mH = dup2(Msm[(16 + b) * 32 + l]);   // LDS.32, 1 wf
                // monarch
                ar0 = fma2(xrL.x, mL, ar0); ar1 = fma2(xrL.y, mL, ar1);
                ar0 = fma2(xrH.x, mH, ar0); ar1 = fma2(xrH.y, mH, ar1);
                aq0 = fma2(xqL.x, mL, aq0); aq1 = fma2(xqL.y, mL, aq1);
                aq0 = fma2(xqH.x, mH, aq0); aq1 = fma2(xqH.y, mH, aq1);
                // block-diag via zero-masked weights (reuses monarch streams)
                const u64 trh = dup2(TrH[b]), trl = dup2(TrL[b]);
                ar0 = fma2(xqH.x, trh, ar0); ar1 = fma2(xqH.y, trh, ar1);
                ar0 = fma2(xqL.x, trl, ar0); ar1 = fma2(xqL.y, trl, ar1);
                const u64 tqh = dup2(TqH[b]), tql = dup2(TqL[b]);
                aq0 = fma2(xrH.x, tqh, aq0); aq1 = fma2(xrH.y, tqh, aq1);
                aq0 = fma2(xrL.x, tql, aq0); aq1 = fma2(xrL.y, tql, aq1);
            }
            // epilogue: out = rs*A + murs*C2 + C1 ; rs via SHFL broadcast
            float* orow = out + base + (size_t)go * 1024;
#pragma unroll
            for (int rp = 0; rp < 2; rp++) {
                const int e = go + 2 * rp;
                const u64 RS2 = pack2(__shfl_sync(~0u, rs_l, e),
                                      __shfl_sync(~0u, rs_l, e + 1));
                const u64 MU2 = pack2(__shfl_sync(~0u, murs_l, e),
                                      __shfl_sync(~0u, murs_l, e + 1));
                const u64 vr = fma2(RS2, rp ? ar1 : ar0, fma2(MU2, dup2(C2r), dup2(C1r)));
                const u64 vq = fma2(RS2, rp ? aq1 : aq0, fma2(MU2, dup2(C2q), dup2(C1q)));
                float A, B;
                unpack2(A, B, vr);
                orow[(2 * rp) * 1024 + 32 * r + l]     = A;
                orow[(2 * rp + 1) * 1024 + 32 * r + l] = B;
                unpack2(A, B, vq);
                orow[(2 * rp) * 1024 + 32 * q + l]     = A;
                orow[(2 * rp + 1) * 1024 + 32 * q + l] = B;
            }
        }
        __syncthreads();
    }
}

// ---------------------------------------------------------------------------
extern "C" void kernel_launch(void* const* d_in, const int* in_sizes, int n_in,
                              void* d_out, int out_size) {
    const float* x     = (const float*)d_in[0];
    const float* gamma = (const float*)d_in[1];
    const float* beta  = (const float*)d_in[2];
    const float* bw    = (const float*)d_in[3];
    const float* wrow  = (const float*)d_in[4];
    const float* wcol  = (const float*)d_in[5];
    const float* alpha = (const float*)d_in[6];
    const float* bias  = (const float*)d_in[7];
    float* out = (float*)d_out;

    const int rows = in_sizes[0] / 1024;
    const int ntiles = rows / 32;

    cudaFuncSetAttribute(hbsl_kernel,
                         cudaFuncAttributeMaxDynamicSharedMemorySize, SMEM_BYTES);
    hbsl_kernel<<<148, THREADS, SMEM_BYTES>>>(x, gamma, beta, bw, wrow, wcol,
                                              alpha, bias, out, ntiles);
}